// round 1
// baseline (speedup 1.0000x reference)
#include <cuda_runtime.h>
#include <cuda_bf16.h>
#include <math_constants.h>

// ---------------------------------------------------------------------------
// MultiHeadAttention: out = MHA(x; Wq,Wk,Wv,Wo), causal + pad mask
//   x: [B=4, S=2048, D=1024] fp32
//   W*: [D_in=1024, D_out=1024] fp32 (row-major, y = x @ W)
//   16 heads, head_dim 64, scale = 1/8
// Round 1: fp32 baseline. 3 kernels:
//   1) qkv_gemm  (z-batched SGEMM 128x128x8)    -> g_Q, g_K, g_V  [b,s,h*64+e]
//   2) attn      (flash-style, 1 thread = 1 query row, online softmax)
//   3) out_gemm  (SGEMM)                         -> d_out
// ---------------------------------------------------------------------------

#define BATCH 4
#define SEQ   2048
#define DM    1024
#define NH    16
#define HD    64
#define MROWS (BATCH * SEQ)   // 8192
#define ATT_SCALE 0.125f      // 1/sqrt(64)

// Scratch (device globals: allocation-free)
__device__ float g_Q[MROWS * DM];
__device__ float g_K[MROWS * DM];
__device__ float g_V[MROWS * DM];
__device__ float g_A[MROWS * DM];

// ------------------------------- SGEMM ------------------------------------
// C[M,N] = A[M,K] @ B[K,N], all row-major. BM=BN=128, BK=8, 256 thr, 8x8/thr.
#define GBM 128
#define GBN 128
#define GBK 8

__device__ __forceinline__ void sgemm_body(const float* __restrict__ A,
                                           const float* __restrict__ B,
                                           float* __restrict__ C,
                                           int M, int N, int K)
{
    __shared__ float As[GBK][GBM];
    __shared__ float Bs[GBK][GBN];

    const int tid = threadIdx.x;
    const int bn  = blockIdx.x;   // N tile
    const int bm  = blockIdx.y;   // M tile

    const float* Ab = A + (size_t)bm * GBM * K;
    const float* Bb = B + (size_t)bn * GBN;

    // A tile loader: 128 rows x 8 cols; thread -> (row = tid/2, col4 = (tid&1)*4)
    const int arow = tid >> 1;
    const int acol = (tid & 1) * 4;
    // B tile loader: 8 rows x 128 cols; thread -> (row = tid/32, col4 = (tid&31)*4)
    const int brow = tid >> 5;
    const int bcol = (tid & 31) * 4;

    const int ty = tid >> 4;   // 0..15
    const int tx = tid & 15;   // 0..15

    float acc[8][8];
#pragma unroll
    for (int i = 0; i < 8; i++)
#pragma unroll
        for (int j = 0; j < 8; j++) acc[i][j] = 0.f;

    for (int k0 = 0; k0 < K; k0 += GBK) {
        float4 av = *(const float4*)(Ab + (size_t)arow * K + k0 + acol);
        float4 bv = *(const float4*)(Bb + (size_t)(k0 + brow) * N + bcol);

        __syncthreads();   // previous iteration's reads complete
        As[acol + 0][arow] = av.x;
        As[acol + 1][arow] = av.y;
        As[acol + 2][arow] = av.z;
        As[acol + 3][arow] = av.w;
        *(float4*)&Bs[brow][bcol] = bv;
        __syncthreads();

#pragma unroll
        for (int kk = 0; kk < GBK; kk++) {
            float af[8], bf[8];
            *(float4*)(af)     = *(const float4*)&As[kk][ty * 8];
            *(float4*)(af + 4) = *(const float4*)&As[kk][ty * 8 + 4];
            *(float4*)(bf)     = *(const float4*)&Bs[kk][tx * 8];
            *(float4*)(bf + 4) = *(const float4*)&Bs[kk][tx * 8 + 4];
#pragma unroll
            for (int i = 0; i < 8; i++)
#pragma unroll
                for (int j = 0; j < 8; j++)
                    acc[i][j] = fmaf(af[i], bf[j], acc[i][j]);
        }
    }

    float* Cb = C + (size_t)bm * GBM * N + (size_t)bn * GBN;
#pragma unroll
    for (int i = 0; i < 8; i++) {
        float4 v0, v1;
        v0.x = acc[i][0]; v0.y = acc[i][1]; v0.z = acc[i][2]; v0.w = acc[i][3];
        v1.x = acc[i][4]; v1.y = acc[i][5]; v1.z = acc[i][6]; v1.w = acc[i][7];
        float* crow = Cb + (size_t)(ty * 8 + i) * N + tx * 8;
        *(float4*)(crow)     = v0;
        *(float4*)(crow + 4) = v1;
    }
}

__global__ __launch_bounds__(256)
void qkv_gemm_kernel(const float* __restrict__ x,
                     const float* __restrict__ Wq,
                     const float* __restrict__ Wk,
                     const float* __restrict__ Wv)
{
    const float* W;
    float* C;
    if (blockIdx.z == 0)      { W = Wq; C = g_Q; }
    else if (blockIdx.z == 1) { W = Wk; C = g_K; }
    else                      { W = Wv; C = g_V; }
    sgemm_body(x, W, C, MROWS, DM, DM);
}

__global__ __launch_bounds__(256)
void out_gemm_kernel(const float* __restrict__ Wo, float* __restrict__ out)
{
    sgemm_body(g_A, Wo, out, MROWS, DM, DM);
}

// ---------------------------- Attention -----------------------------------
// grid: (SEQ/128, BATCH*NH), block 128. Thread owns one query row.
// Online softmax is fully thread-local. K/V tiles (64x64 f32) staged in smem,
// broadcast-read by all lanes.
__global__ __launch_bounds__(128)
void attn_kernel(const unsigned char* __restrict__ pad)
{
    __shared__ float Ks[64][64];
    __shared__ float Vs[64][64];
    __shared__ unsigned char pm[64];

    const int tid = threadIdx.x;
    const int b   = blockIdx.y >> 4;
    const int h   = blockIdx.y & 15;
    const int i   = blockIdx.x * 128 + tid;        // global query position

    const float* Qrow = g_Q + (size_t)(b * SEQ + i) * DM + h * HD;
    float q[HD];
#pragma unroll
    for (int d4 = 0; d4 < 16; d4++) {
        float4 v = *(const float4*)(Qrow + d4 * 4);
        q[d4 * 4 + 0] = v.x * ATT_SCALE;
        q[d4 * 4 + 1] = v.y * ATT_SCALE;
        q[d4 * 4 + 2] = v.z * ATT_SCALE;
        q[d4 * 4 + 3] = v.w * ATT_SCALE;
    }

    float o[HD];
#pragma unroll
    for (int d = 0; d < HD; d++) o[d] = 0.f;
    float m = -CUDART_INF_F;
    float l = 0.f;

    const int ntiles = blockIdx.x * 2 + 2;         // last key tile touching this block

    for (int kt = 0; kt < ntiles; kt++) {
        const int k0 = kt * 64;
        const float* Kb = g_K + (size_t)(b * SEQ + k0) * DM + h * HD;
        const float* Vb = g_V + (size_t)(b * SEQ + k0) * DM + h * HD;

#pragma unroll
        for (int r = 0; r < 8; r++) {
            int f   = r * 128 + tid;               // 0..1023 float4 slots
            int row = f >> 4;
            int c4  = (f & 15) * 4;
            *(float4*)&Ks[row][c4] = *(const float4*)(Kb + (size_t)row * DM + c4);
            *(float4*)&Vs[row][c4] = *(const float4*)(Vb + (size_t)row * DM + c4);
        }
        if (tid < 64) pm[tid] = pad[b * SEQ + k0 + tid];
        __syncthreads();

        int jmax = i - k0 + 1;                     // causal: key k0+j <= i
        if (jmax > 64) jmax = 64;

        for (int j = 0; j < jmax; j++) {
            if (pm[j]) continue;
            float s = 0.f;
#pragma unroll
            for (int d4 = 0; d4 < 16; d4++) {
                float4 kv = *(const float4*)&Ks[j][d4 * 4];
                s += q[d4 * 4 + 0] * kv.x;
                s += q[d4 * 4 + 1] * kv.y;
                s += q[d4 * 4 + 2] * kv.z;
                s += q[d4 * 4 + 3] * kv.w;
            }
            if (s > m) {                            // rare after warm-up
                float alpha = __expf(m - s);        // m=-inf -> alpha=0 first time
                m = s;
                l *= alpha;
#pragma unroll
                for (int d = 0; d < HD; d++) o[d] *= alpha;
            }
            float p = __expf(s - m);
            l += p;
#pragma unroll
            for (int d4 = 0; d4 < 16; d4++) {
                float4 vv = *(const float4*)&Vs[j][d4 * 4];
                o[d4 * 4 + 0] = fmaf(p, vv.x, o[d4 * 4 + 0]);
                o[d4 * 4 + 1] = fmaf(p, vv.y, o[d4 * 4 + 1]);
                o[d4 * 4 + 2] = fmaf(p, vv.z, o[d4 * 4 + 2]);
                o[d4 * 4 + 3] = fmaf(p, vv.w, o[d4 * 4 + 3]);
            }
        }
        __syncthreads();
    }

    float inv = (l > 0.f) ? (1.f / l) : 0.f;
    float* Orow = g_A + (size_t)(b * SEQ + i) * DM + h * HD;
#pragma unroll
    for (int d4 = 0; d4 < 16; d4++) {
        float4 v;
        v.x = o[d4 * 4 + 0] * inv;
        v.y = o[d4 * 4 + 1] * inv;
        v.z = o[d4 * 4 + 2] * inv;
        v.w = o[d4 * 4 + 3] * inv;
        *(float4*)(Orow + d4 * 4) = v;
    }
}

// ------------------------------ Launch -------------------------------------
extern "C" void kernel_launch(void* const* d_in, const int* in_sizes, int n_in,
                              void* d_out, int out_size)
{
    (void)in_sizes; (void)n_in; (void)out_size;
    const float*         x   = (const float*)d_in[0];
    const unsigned char* pad = (const unsigned char*)d_in[1];
    const float*         Wq  = (const float*)d_in[2];
    const float*         Wk  = (const float*)d_in[3];
    const float*         Wv  = (const float*)d_in[4];
    const float*         Wo  = (const float*)d_in[5];
    float*               out = (float*)d_out;

    dim3 gQKV(DM / GBN, MROWS / GBM, 3);     // (8, 64, 3)
    qkv_gemm_kernel<<<gQKV, 256>>>(x, Wq, Wk, Wv);

    dim3 gATT(SEQ / 128, BATCH * NH);        // (16, 64)
    attn_kernel<<<gATT, 128>>>(pad);

    dim3 gOUT(DM / GBN, MROWS / GBM);        // (8, 64)
    out_gemm_kernel<<<gOUT, 256>>>(Wo, out);
}